// round 3
// baseline (speedup 1.0000x reference)
#include <cuda_runtime.h>
#include <cuda_bf16.h>
#include <math.h>

// Problem constants (fixed shapes)
#define BB 8
#define HH 13
#define WW 13
#define AA 5
#define CC 20
#define NN (BB*HH*WW*AA)   // 6760

static __constant__ float c_anchors[2*AA] = {
    1.3221f, 1.73145f,
    3.19275f, 4.00944f,
    5.05587f, 8.09892f,
    9.47112f, 4.84053f,
    11.2364f, 10.0071f
};

// Scratch (device globals — no allocation allowed)
__device__ float4 g_pred[NN];     // decoded pred boxes (x,y,w,h)
__device__ float4 g_posbox[NN];   // compacted decoded gt boxes of positive anchors
__device__ int    g_npos;         // number of positives

__device__ __forceinline__ float block_reduce_sum(float v) {
    __shared__ float sh[32];
    int lane = threadIdx.x & 31;
    int wid  = threadIdx.x >> 5;
    #pragma unroll
    for (int off = 16; off > 0; off >>= 1)
        v += __shfl_down_sync(0xffffffffu, v, off);
    if (lane == 0) sh[wid] = v;
    __syncthreads();
    int nwarps = (blockDim.x + 31) >> 5;
    v = (threadIdx.x < nwarps) ? sh[threadIdx.x] : 0.f;
    if (wid == 0) {
        #pragma unroll
        for (int off = 16; off > 0; off >>= 1)
            v += __shfl_down_sync(0xffffffffu, v, off);
    }
    return v;  // valid in thread 0
}

__device__ __forceinline__ float huber(float d) {
    float ad = fabsf(d);
    return (ad < 1.0f) ? 0.5f * d * d : ad - 0.5f;
}

// Kernel 1: per-anchor losses + box decode + positive compaction
__global__ void __launch_bounds__(256)
k1_peranchor(const float* __restrict__ pred_cls,
             const float* __restrict__ pred_conf,
             const float* __restrict__ pred_bb,
             const float* __restrict__ label_cls,
             const float* __restrict__ label_conf,
             const float* __restrict__ label_bb,
             float* __restrict__ out)
{
    int j = blockIdx.x * blockDim.x + threadIdx.x;
    float local = 0.f;

    if (j < NN) {
        // index decode: layout (B,H,W,A)
        int a = j % AA;
        int w = (j / AA) % WW;
        int h = (j / (AA * WW)) % HH;

        const float inv = 1.0f / 13.0f;   // fs0 = fs1 = 13
        float anc_x = (float)w;           // grid stacks [xs, ys] -> x = col
        float anc_y = (float)h;
        float anc_w = c_anchors[2*a];
        float anc_h = c_anchors[2*a + 1];

        // decode pred box
        float p0 = pred_bb[4*j + 0], p1 = pred_bb[4*j + 1];
        float p2 = pred_bb[4*j + 2], p3 = pred_bb[4*j + 3];
        float pw = expf(p2) * anc_w * inv;
        float ph = expf(p3) * anc_h * inv;
        float px = (p0 + anc_x) * inv - 0.5f * pw;
        float py = (p1 + anc_y) * inv - 0.5f * ph;
        g_pred[j] = make_float4(px, py, pw, ph);

        bool pos = label_conf[j] > 0.f;
        if (pos) {
            // decode gt box
            float l0 = label_bb[4*j + 0], l1 = label_bb[4*j + 1];
            float l2 = label_bb[4*j + 2], l3 = label_bb[4*j + 3];
            float gw = expf(l2) * anc_w * inv;
            float gh = expf(l3) * anc_h * inv;
            float gx = (l0 + anc_x) * inv - 0.5f * gw;
            float gy = (l1 + anc_y) * inv - 0.5f * gh;

            int slot = atomicAdd(&g_npos, 1);
            g_posbox[slot] = make_float4(gx, gy, gw, gh);

            // diagonal IoU (gt vs pred)
            float gx2 = gx + gw, gy2 = gy + gh;
            float px2 = px + pw, py2 = py + ph;
            float dxI = fmaxf(fminf(gx2, px2) - fmaxf(gx, px), 0.f);
            float dyI = fmaxf(fminf(gy2, py2) - fmaxf(gy, py), 0.f);
            float inter = dxI * dyI;
            float iou = inter / (gw * gh + pw * ph - inter);

            // positive-conf loss: OBJ_SCALE/B = 5/8
            float pc = pred_conf[j];
            float dconf = pc - iou;
            local += dconf * dconf * (5.0f / 8.0f);

            // coord losses: L_COORD/B = 3/8
            float dx = p0 - l0, dy = p1 - l1;
            local += (dx*dx + dy*dy) * (3.0f / 8.0f);
            float dw = p2 - l2, dh = p3 - l3;
            local += (huber(dw) + huber(dh)) * (3.0f / 8.0f);

            // class NLL: argmax(label_cls) then -log_softmax(pred_cls)[lbl]
            const float* lc = label_cls + (size_t)CC * j;
            const float* pcl = pred_cls + (size_t)CC * j;
            int lbl = 0;
            float bm = lc[0];
            float mx = pcl[0];
            #pragma unroll
            for (int c = 1; c < CC; c++) {
                float lv = lc[c];
                if (lv > bm) { bm = lv; lbl = c; }
                mx = fmaxf(mx, pcl[c]);
            }
            float s = 0.f;
            #pragma unroll
            for (int c = 0; c < CC; c++) s += expf(pcl[c] - mx);
            float nll = -(pcl[lbl] - mx - logf(s));
            local += nll * (1.0f / 8.0f);
        }
    }

    float bs = block_reduce_sum(local);
    if (threadIdx.x == 0 && bs != 0.f) atomicAdd(out, bs);
    else if (threadIdx.x == 0) atomicAdd(out, bs); // keep deterministic op count
}

// Kernel 2: best-IoU-over-positives per pred box, negative-conf loss
__global__ void __launch_bounds__(256)
k2_negconf(const float* __restrict__ pred_conf,
           const float* __restrict__ label_conf,
           float* __restrict__ out)
{
    __shared__ float4 tile[256];
    int j = blockIdx.x * blockDim.x + threadIdx.x;

    float4 p = make_float4(0.f, 0.f, 0.f, 0.f);
    if (j < NN) p = g_pred[j];
    float px2 = p.x + p.z, py2 = p.y + p.w;
    float pa = p.z * p.w;

    int npos = g_npos;
    float best = 0.f;

    for (int base = 0; base < npos; base += 256) {
        int cnt = min(256, npos - base);
        if ((int)threadIdx.x < cnt) tile[threadIdx.x] = g_posbox[base + threadIdx.x];
        __syncthreads();
        for (int t = 0; t < cnt; t++) {
            float4 g = tile[t];
            float gx2 = g.x + g.z, gy2 = g.y + g.w;
            float dxI = fmaxf(fminf(gx2, px2) - fmaxf(g.x, p.x), 0.f);
            float dyI = fmaxf(fminf(gy2, py2) - fmaxf(g.y, p.y), 0.f);
            float inter = dxI * dyI;
            float iou = inter / (g.z * g.w + pa - inter);
            best = fmaxf(best, iou);
        }
        __syncthreads();
    }

    float local = 0.f;
    if (j < NN) {
        bool pos = label_conf[j] > 0.f;   // best := 1 for positives -> negf = 0
        if (!pos && best < 0.6f) {
            float d = pred_conf[j] - label_conf[j];
            local = d * d * (1.0f / 8.0f);   // NOOBJ_SCALE/B
        }
    }

    float bs = block_reduce_sum(local);
    if (threadIdx.x == 0) atomicAdd(out, bs);
}

extern "C" void kernel_launch(void* const* d_in, const int* in_sizes, int n_in,
                              void* d_out, int out_size)
{
    const float* pred_cls   = (const float*)d_in[0];
    const float* pred_conf  = (const float*)d_in[1];
    const float* pred_bb    = (const float*)d_in[2];
    const float* label_cls  = (const float*)d_in[3];
    const float* label_conf = (const float*)d_in[4];
    const float* label_bb   = (const float*)d_in[5];
    float* out = (float*)d_out;

    // zero output scalar + positive counter (both graph-capturable async memsets)
    cudaMemsetAsync(out, 0, sizeof(float));
    static int* npos_addr = nullptr;
    if (!npos_addr) cudaGetSymbolAddress((void**)&npos_addr, g_npos);
    cudaMemsetAsync(npos_addr, 0, sizeof(int));

    const int threads = 256;
    const int blocks = (NN + threads - 1) / threads;  // 27

    k1_peranchor<<<blocks, threads>>>(pred_cls, pred_conf, pred_bb,
                                      label_cls, label_conf, label_bb, out);
    k2_negconf<<<blocks, threads>>>(pred_conf, label_conf, out);
}

// round 5
// speedup vs baseline: 1.7550x; 1.7550x over previous
#include <cuda_runtime.h>
#include <cuda_bf16.h>
#include <math.h>

// Fixed problem shape: B=8, H=W=13, A=5, C=20
#define NN   6760          // B*H*W*A
#define NN4  (NN/4)        // 1690
#define NBLK 845           // NN / 8 warps-per-block
#define MAXPOS 512         // ~135 expected positives (2%), 33-sigma headroom

static __constant__ float c_anchors[10] = {
    1.3221f, 1.73145f,
    3.19275f, 4.00944f,
    5.05587f, 8.09892f,
    9.47112f, 4.84053f,
    11.2364f, 10.0071f
};

__device__ __forceinline__ float huber(float d) {
    float ad = fabsf(d);
    return (ad < 1.0f) ? 0.5f * d * d : ad - 0.5f;
}

// One fused kernel. Each block:
//  Phase A: scans label_conf (float4), compacts + decodes positive gt boxes to smem.
//  Phase B: warp w owns pred j = blockIdx*8+w; lanes split the positives for the
//           best-IoU max; lane 0 adds either the positive-anchor losses or the
//           negative-conf loss. Block-reduce, one atomicAdd.
__global__ void __launch_bounds__(256)
yolo_fused(const float* __restrict__ pred_cls,
           const float* __restrict__ pred_conf,
           const float* __restrict__ pred_bb,
           const float* __restrict__ label_cls,
           const float* __restrict__ label_conf,
           const float* __restrict__ label_bb,
           float* __restrict__ out)
{
    __shared__ float4 s_pos[MAXPOS];
    __shared__ int    s_cnt;
    __shared__ float  s_red[8];

    const float inv = 1.0f / 13.0f;   // fs0 = fs1 = 13
    const float4* lbb4 = (const float4*)label_bb;
    const float4* pbb4 = (const float4*)pred_bb;
    const float4* lc4  = (const float4*)label_conf;

    if (threadIdx.x == 0) s_cnt = 0;
    __syncthreads();

    // ---------- Phase A: compact + decode positive gt boxes ----------
    for (int i4 = threadIdx.x; i4 < NN4; i4 += 256) {
        float4 c = lc4[i4];
        float cv[4] = {c.x, c.y, c.z, c.w};
        #pragma unroll
        for (int s = 0; s < 4; s++) {
            if (cv[s] > 0.f) {
                int idx = i4 * 4 + s;
                int a = idx % 5;
                int w = (idx / 5)  % 13;
                int h = (idx / 65) % 13;
                float4 l = lbb4[idx];
                float gw = expf(l.z) * c_anchors[2*a]     * inv;
                float gh = expf(l.w) * c_anchors[2*a + 1] * inv;
                float gx = (l.x + (float)w) * inv - 0.5f * gw;
                float gy = (l.y + (float)h) * inv - 0.5f * gh;
                int slot = atomicAdd(&s_cnt, 1);
                if (slot < MAXPOS) s_pos[slot] = make_float4(gx, gy, gw, gh);
            }
        }
    }
    __syncthreads();
    int npos = min(s_cnt, MAXPOS);

    // ---------- Phase B: warp-per-pred ----------
    int lane = threadIdx.x & 31;
    int wid  = threadIdx.x >> 5;
    int j    = blockIdx.x * 8 + wid;   // 845*8 == 6760 exactly

    float local = 0.f;

    // decode this warp's pred box (all lanes redundantly; L1 broadcast)
    float4 p = pbb4[j];
    int a = j % 5;
    int w = (j / 5)  % 13;
    int h = (j / 65) % 13;
    float anc_w = c_anchors[2*a], anc_h = c_anchors[2*a + 1];
    float pw = expf(p.z) * anc_w * inv;
    float ph = expf(p.w) * anc_h * inv;
    float px = (p.x + (float)w) * inv - 0.5f * pw;
    float py = (p.y + (float)h) * inv - 0.5f * ph;
    float px2 = px + pw, py2 = py + ph;
    float a2  = (px2 - px) * (py2 - py);   // mirror pairwise_iou's area expr

    // best IoU over positives, lanes strided
    float best = 0.f;
    for (int k = lane; k < npos; k += 32) {
        float4 g = s_pos[k];
        float gx2 = g.x + g.z, gy2 = g.y + g.w;
        float dx = fmaxf(fminf(gx2, px2) - fmaxf(g.x, px), 0.f);
        float dy = fmaxf(fminf(gy2, py2) - fmaxf(g.y, py), 0.f);
        float inter = dx * dy;
        float a1 = (gx2 - g.x) * (gy2 - g.y);
        best = fmaxf(best, inter / (a1 + a2 - inter));
    }
    #pragma unroll
    for (int off = 16; off > 0; off >>= 1)
        best = fmaxf(best, __shfl_xor_sync(0xffffffffu, best, off));

    if (lane == 0) {
        float lconf = label_conf[j];
        if (lconf > 0.f) {
            // ---- positive-anchor losses ----
            float4 l = lbb4[j];
            float gw = expf(l.z) * anc_w * inv;
            float gh = expf(l.w) * anc_h * inv;
            float gx = (l.x + (float)w) * inv - 0.5f * gw;
            float gy = (l.y + (float)h) * inv - 0.5f * gh;

            // diag IoU (elem_iou uses w*h areas)
            float gx2 = gx + gw, gy2 = gy + gh;
            float dx = fmaxf(fminf(gx2, px2) - fmaxf(gx, px), 0.f);
            float dy = fmaxf(fminf(gy2, py2) - fmaxf(gy, py), 0.f);
            float inter = dx * dy;
            float iou = inter / (gw * gh + pw * ph - inter);

            float dc = pred_conf[j] - iou;
            local += dc * dc * (5.0f / 8.0f);                       // OBJ_SCALE/B

            float ddx = p.x - l.x, ddy = p.y - l.y;
            local += (ddx * ddx + ddy * ddy) * (3.0f / 8.0f);       // L_COORD/B
            local += (huber(p.z - l.z) + huber(p.w - l.w)) * (3.0f / 8.0f);

            // class NLL: argmax(label_cls) (first-max), -log_softmax(pred_cls)
            const float* lcr = label_cls + 20 * j;
            const float* pcr = pred_cls  + 20 * j;
            int lbl = 0;
            float bm = lcr[0];
            float mx = pcr[0];
            #pragma unroll
            for (int c = 1; c < 20; c++) {
                float lv = lcr[c];
                if (lv > bm) { bm = lv; lbl = c; }
                mx = fmaxf(mx, pcr[c]);
            }
            float ssum = 0.f;
            #pragma unroll
            for (int c = 0; c < 20; c++) ssum += expf(pcr[c] - mx);
            local += -(pcr[lbl] - mx - logf(ssum)) * (1.0f / 8.0f);
        } else if (best < 0.6f) {
            // ---- negative-conf loss ---- (positives excluded: ref sets best=1)
            float d = pred_conf[j] - lconf;
            local += d * d * (1.0f / 8.0f);                          // NOOBJ_SCALE/B
        }
    }

    // ---------- block reduction + single atomic ----------
    #pragma unroll
    for (int off = 16; off > 0; off >>= 1)
        local += __shfl_down_sync(0xffffffffu, local, off);
    if (lane == 0) s_red[wid] = local;
    __syncthreads();
    if (wid == 0) {
        float v = (lane < 8) ? s_red[lane] : 0.f;
        #pragma unroll
        for (int off = 4; off > 0; off >>= 1)
            v += __shfl_down_sync(0xffffffffu, v, off);
        if (lane == 0) atomicAdd(out, v);
    }
}

extern "C" void kernel_launch(void* const* d_in, const int* in_sizes, int n_in,
                              void* d_out, int out_size)
{
    const float* pred_cls   = (const float*)d_in[0];
    const float* pred_conf  = (const float*)d_in[1];
    const float* pred_bb    = (const float*)d_in[2];
    const float* label_cls  = (const float*)d_in[3];
    const float* label_conf = (const float*)d_in[4];
    const float* label_bb   = (const float*)d_in[5];
    float* out = (float*)d_out;

    cudaMemsetAsync(out, 0, sizeof(float));
    yolo_fused<<<NBLK, 256>>>(pred_cls, pred_conf, pred_bb,
                              label_cls, label_conf, label_bb, out);
}

// round 8
// speedup vs baseline: 2.7378x; 1.5600x over previous
#include <cuda_runtime.h>
#include <cuda_bf16.h>
#include <math.h>

// Fixed problem shape: B=8, H=W=13, A=5, C=20
#define NN     6760       // B*H*W*A
#define NN4    1690       // NN/4
#define NBLK   106        // single wave on 148 SMs
#define PPB    64         // preds per block  (106*64 = 6784 >= 6760)
#define LPG    4          // lanes per pred group (64*4 = 256 threads)
#define MAXPOS 512        // ~135 expected positives (2%)

static __constant__ float c_anchors[10] = {
    1.3221f, 1.73145f,
    3.19275f, 4.00944f,
    5.05587f, 8.09892f,
    9.47112f, 4.84053f,
    11.2364f, 10.0071f
};

// Grid-reduction scratch (zero-initialized at module load; reset by last block)
__device__ float    g_sum     = 0.f;
__device__ unsigned g_tickets = 0u;

__device__ __forceinline__ float huber(float d) {
    float ad = fabsf(d);
    return (ad < 1.0f) ? 0.5f * d * d : ad - 0.5f;
}

__global__ void __launch_bounds__(256)
yolo_one(const float* __restrict__ pred_cls,
         const float* __restrict__ pred_conf,
         const float* __restrict__ pred_bb,
         const float* __restrict__ label_cls,
         const float* __restrict__ label_conf,
         const float* __restrict__ label_bb,
         float* __restrict__ out)
{
    __shared__ float4 s_pos[MAXPOS];   // (gx, gy, gx2, gy2)
    __shared__ float  s_c[MAXPOS];     // 0.6 * a1  (pairwise-area convention)
    __shared__ int    s_cnt;
    __shared__ float  s_red[8];

    const float inv = 1.0f / 13.0f;
    const float4* lbb4 = (const float4*)label_bb;
    const float4* pbb4 = (const float4*)pred_bb;
    const float4* lc4  = (const float4*)label_conf;

    if (threadIdx.x == 0) s_cnt = 0;
    __syncthreads();

    // ---------- Phase A: compact + decode positive gt boxes into smem ----------
    for (int i4 = threadIdx.x; i4 < NN4; i4 += 256) {
        float4 c = lc4[i4];
        float cv[4] = {c.x, c.y, c.z, c.w};
        #pragma unroll
        for (int s = 0; s < 4; s++) {
            if (cv[s] > 0.f) {
                int idx = i4 * 4 + s;
                int a = idx % 5;
                int w = (idx / 5)  % 13;
                int h = (idx / 65) % 13;
                float4 l = lbb4[idx];
                float gw = __expf(l.z) * c_anchors[2*a]     * inv;
                float gh = __expf(l.w) * c_anchors[2*a + 1] * inv;
                float gx = (l.x + (float)w) * inv - 0.5f * gw;
                float gy = (l.y + (float)h) * inv - 0.5f * gh;
                float gx2 = gx + gw, gy2 = gy + gh;
                int slot = atomicAdd(&s_cnt, 1);
                if (slot < MAXPOS) {
                    s_pos[slot] = make_float4(gx, gy, gx2, gy2);
                    s_c[slot]   = 0.6f * ((gx2 - gx) * (gy2 - gy));
                }
            }
        }
    }
    __syncthreads();
    int npos = min(s_cnt, MAXPOS);

    // ---------- Phase B: 4-lane groups, one pred each ----------
    int g  = threadIdx.x & (LPG - 1);
    int pr = threadIdx.x >> 2;                 // 0..63
    int j  = blockIdx.x * PPB + pr;
    bool valid = j < NN;

    float local = 0.f;
    float bestm = -1e30f;
    float px = 0.f, py = 0.f, px2 = 0.f, py2 = 0.f, cp = 0.f;
    float4 p = make_float4(0.f, 0.f, 0.f, 0.f);
    float anc_w = 0.f, anc_h = 0.f;
    int w = 0, h = 0;

    if (valid) {
        p = pbb4[j];
        int a = j % 5;
        w = (j / 5)  % 13;
        h = (j / 65) % 13;
        anc_w = c_anchors[2*a]; anc_h = c_anchors[2*a + 1];
        float pw = __expf(p.z) * anc_w * inv;
        float ph = __expf(p.w) * anc_h * inv;
        px = (p.x + (float)w) * inv - 0.5f * pw;
        py = (p.y + (float)h) * inv - 0.5f * ph;
        px2 = px + pw; py2 = py + ph;
        cp = 0.6f * ((px2 - px) * (py2 - py));   // 0.6 * a2 (pairwise convention)

        // division-free threshold loop:  iou<0.6  <=>  1.6*inter - 0.6*a1 < 0.6*a2
        for (int k = g; k < npos; k += LPG) {
            float4 gb = s_pos[k];
            float dx = fmaxf(fminf(gb.z, px2) - fmaxf(gb.x, px), 0.f);
            float dy = fmaxf(fminf(gb.w, py2) - fmaxf(gb.y, py), 0.f);
            bestm = fmaxf(bestm, fmaf(1.6f, dx * dy, -s_c[k]));
        }
    }
    // 4-lane max (all lanes participate)
    bestm = fmaxf(bestm, __shfl_xor_sync(0xffffffffu, bestm, 1, LPG));
    bestm = fmaxf(bestm, __shfl_xor_sync(0xffffffffu, bestm, 2, LPG));

    if (g == 0 && valid) {
        float lconf = label_conf[j];
        if (lconf > 0.f) {
            // ---- positive-anchor losses ----
            float4 l = lbb4[j];
            float gw = __expf(l.z) * anc_w * inv;
            float gh = __expf(l.w) * anc_h * inv;
            float gx = (l.x + (float)w) * inv - 0.5f * gw;
            float gy = (l.y + (float)h) * inv - 0.5f * gh;

            // diag IoU (elem_iou: areas = w*h), true division here (rare path)
            float gx2 = gx + gw, gy2 = gy + gh;
            float pw = px2 - px, ph = py2 - py;
            float dx = fmaxf(fminf(gx2, px2) - fmaxf(gx, px), 0.f);
            float dy = fmaxf(fminf(gy2, py2) - fmaxf(gy, py), 0.f);
            float inter = dx * dy;
            float iou = inter / (gw * gh + pw * ph - inter);

            float dc = pred_conf[j] - iou;
            local += dc * dc * (5.0f / 8.0f);                       // OBJ_SCALE/B

            float ddx = p.x - l.x, ddy = p.y - l.y;
            local += (ddx * ddx + ddy * ddy) * (3.0f / 8.0f);       // L_COORD/B
            local += (huber(p.z - l.z) + huber(p.w - l.w)) * (3.0f / 8.0f);

            // class NLL: first-max argmax(label_cls), -log_softmax(pred_cls)[lbl]
            const float* lcr = label_cls + 20 * j;
            const float* pcr = pred_cls  + 20 * j;
            int lbl = 0;
            float bm = lcr[0];
            float mx = pcr[0];
            #pragma unroll
            for (int c = 1; c < 20; c++) {
                float lv = lcr[c];
                if (lv > bm) { bm = lv; lbl = c; }
                mx = fmaxf(mx, pcr[c]);
            }
            float ssum = 0.f;
            #pragma unroll
            for (int c = 0; c < 20; c++) ssum += __expf(pcr[c] - mx);
            local += -(pcr[lbl] - mx - logf(ssum)) * (1.0f / 8.0f);
        } else if (bestm < cp) {
            // ---- negative-conf loss ---- (positives excluded per reference)
            float d = pred_conf[j] - lconf;
            local += d * d * (1.0f / 8.0f);                          // NOOBJ_SCALE/B
        }
    }

    // ---------- block reduction ----------
    int lane = threadIdx.x & 31;
    int wid  = threadIdx.x >> 5;
    #pragma unroll
    for (int off = 16; off > 0; off >>= 1)
        local += __shfl_down_sync(0xffffffffu, local, off);
    if (lane == 0) s_red[wid] = local;
    __syncthreads();

    if (wid == 0) {
        float v = (lane < 8) ? s_red[lane] : 0.f;
        #pragma unroll
        for (int off = 4; off > 0; off >>= 1)
            v += __shfl_down_sync(0xffffffffu, v, off);
        if (lane == 0) {
            // ---------- grid reduction: last block writes + resets ----------
            atomicAdd(&g_sum, v);
            __threadfence();
            unsigned t = atomicAdd(&g_tickets, 1u);
            if (t == (unsigned)(gridDim.x - 1)) {
                float total = atomicExch(&g_sum, 0.f);
                atomicExch(&g_tickets, 0u);
                *out = total;
            }
        }
    }
}

extern "C" void kernel_launch(void* const* d_in, const int* in_sizes, int n_in,
                              void* d_out, int out_size)
{
    const float* pred_cls   = (const float*)d_in[0];
    const float* pred_conf  = (const float*)d_in[1];
    const float* pred_bb    = (const float*)d_in[2];
    const float* label_cls  = (const float*)d_in[3];
    const float* label_conf = (const float*)d_in[4];
    const float* label_bb   = (const float*)d_in[5];
    float* out = (float*)d_out;

    yolo_one<<<NBLK, 256>>>(pred_cls, pred_conf, pred_bb,
                            label_cls, label_conf, label_bb, out);
}

// round 10
// speedup vs baseline: 3.0800x; 1.1250x over previous
#include <cuda_runtime.h>
#include <cuda_bf16.h>
#include <math.h>

// Fixed problem shape: B=8, H=W=13, A=5, C=20
#define NN     6760       // B*H*W*A
#define NN4    1690       // NN/4
#define NBLK   106        // single wave
#define NT     512        // threads per block
#define PPB    64         // preds per block  (106*64 = 6784 >= 6760)
#define LPG    8          // lanes per pred group (64*8 = 512)
#define MAXPOS 512

static __constant__ float c_anchors[10] = {
    1.3221f, 1.73145f,
    3.19275f, 4.00944f,
    5.05587f, 8.09892f,
    9.47112f, 4.84053f,
    11.2364f, 10.0071f
};

// Grid-reduction scratch (zero-init at load; last block resets -> replay-safe)
__device__ float    g_sum     = 0.f;
__device__ unsigned g_tickets = 0u;

__device__ __forceinline__ float huber(float d) {
    float ad = fabsf(d);
    return (ad < 1.0f) ? 0.5f * d * d : ad - 0.5f;
}

__global__ void __launch_bounds__(NT)
yolo_one(const float* __restrict__ pred_cls,
         const float* __restrict__ pred_conf,
         const float* __restrict__ pred_bb,
         const float* __restrict__ label_cls,
         const float* __restrict__ label_conf,
         const float* __restrict__ label_bb,
         float* __restrict__ out)
{
    __shared__ float4 s_pos[MAXPOS];   // (gx, gy, gx2, gy2)
    __shared__ float  s_c[MAXPOS];     // 0.6 * a1
    __shared__ int    s_cnt;
    __shared__ float  s_red[16];

    const float inv = 1.0f / 13.0f;
    const float4* lbb4 = (const float4*)label_bb;
    const float4* pbb4 = (const float4*)pred_bb;
    const float4* lc4  = (const float4*)label_conf;

    int tid = threadIdx.x;
    if (tid == 0) s_cnt = 0;

    // group/pred ids for Phase B
    int g  = tid & (LPG - 1);
    int pr = tid >> 3;                  // 0..63
    int j  = blockIdx.x * PPB + pr;
    bool valid = j < NN;

    // ---- prefetch EVERYTHING independent up front (max MLP, no dependent hops) ----
    float4 p = make_float4(0.f, 0.f, 0.f, 0.f);
    if (valid) p = pbb4[j];             // pred box (L2) in flight during Phase A

    float4 cbuf[4], bbuf[4];
    #pragma unroll
    for (int t = 0; t < 4; t++) {
        int i4 = tid + t * NT;
        if (i4 < NN4) { cbuf[t] = lc4[i4]; bbuf[t] = lbb4[i4 * 4 + 0]; }
    }
    // NOTE: bbuf[t] above prefetches only the first sub-box of the quad; positives
    // within a quad still need their own lbb4[idx]. Instead prefetch nothing
    // speculative per-sub — handle below with conf first, boxes as needed but
    // issued immediately after conf arrives (conf loads were batched).
    __syncthreads();   // s_cnt=0 visible

    // ---------- Phase A: compact + decode positive gt boxes ----------
    #pragma unroll
    for (int t = 0; t < 4; t++) {
        int i4 = tid + t * NT;
        if (i4 >= NN4) break;
        float4 c = cbuf[t];
        float cv[4] = {c.x, c.y, c.z, c.w};
        #pragma unroll
        for (int s = 0; s < 4; s++) {
            if (cv[s] > 0.f) {
                int idx = i4 * 4 + s;
                int a = idx % 5;
                int w = (idx / 5)  % 13;
                int h = (idx / 65) % 13;
                float4 l = (s == 0) ? bbuf[t] : lbb4[idx];
                float gw = __expf(l.z) * c_anchors[2*a]     * inv;
                float gh = __expf(l.w) * c_anchors[2*a + 1] * inv;
                float gx = (l.x + (float)w) * inv - 0.5f * gw;
                float gy = (l.y + (float)h) * inv - 0.5f * gh;
                float gx2 = gx + gw, gy2 = gy + gh;
                int slot = atomicAdd(&s_cnt, 1);
                if (slot < MAXPOS) {
                    s_pos[slot] = make_float4(gx, gy, gx2, gy2);
                    s_c[slot]   = 0.6f * ((gx2 - gx) * (gy2 - gy));
                }
            }
        }
    }
    __syncthreads();
    int npos = min(s_cnt, MAXPOS);

    // ---------- Phase B: 8-lane groups, one pred each ----------
    float local = 0.f;
    float bestm = -1e30f;
    float px = 0.f, py = 0.f, px2 = 0.f, py2 = 0.f, cp = 0.f;
    float anc_w = 0.f, anc_h = 0.f;
    int w = 0, h = 0;

    if (valid) {
        int a = j % 5;
        w = (j / 5)  % 13;
        h = (j / 65) % 13;
        anc_w = c_anchors[2*a]; anc_h = c_anchors[2*a + 1];
        float pw = __expf(p.z) * anc_w * inv;
        float ph = __expf(p.w) * anc_h * inv;
        px = (p.x + (float)w) * inv - 0.5f * pw;
        py = (p.y + (float)h) * inv - 0.5f * ph;
        px2 = px + pw; py2 = py + ph;
        cp = 0.6f * ((px2 - px) * (py2 - py));

        // division-free: iou<0.6  <=>  max(1.6*inter - 0.6*a1) < 0.6*a2
        for (int k = g; k < npos; k += LPG) {
            float4 gb = s_pos[k];
            float dx = fmaxf(fminf(gb.z, px2) - fmaxf(gb.x, px), 0.f);
            float dy = fmaxf(fminf(gb.w, py2) - fmaxf(gb.y, py), 0.f);
            bestm = fmaxf(bestm, fmaf(1.6f, dx * dy, -s_c[k]));
        }
    }
    bestm = fmaxf(bestm, __shfl_xor_sync(0xffffffffu, bestm, 1, LPG));
    bestm = fmaxf(bestm, __shfl_xor_sync(0xffffffffu, bestm, 2, LPG));
    bestm = fmaxf(bestm, __shfl_xor_sync(0xffffffffu, bestm, 4, LPG));

    if (g == 0 && valid) {
        float lconf = label_conf[j];
        if (lconf > 0.f) {
            // ---- positive-anchor losses (rare: ~2%) ----
            float4 l = lbb4[j];
            float gw = __expf(l.z) * anc_w * inv;
            float gh = __expf(l.w) * anc_h * inv;
            float gx = (l.x + (float)w) * inv - 0.5f * gw;
            float gy = (l.y + (float)h) * inv - 0.5f * gh;

            float gx2 = gx + gw, gy2 = gy + gh;
            float pw = px2 - px, ph = py2 - py;
            float dx = fmaxf(fminf(gx2, px2) - fmaxf(gx, px), 0.f);
            float dy = fmaxf(fminf(gy2, py2) - fmaxf(gy, py), 0.f);
            float inter = dx * dy;
            float iou = inter / (gw * gh + pw * ph - inter);

            float dc = pred_conf[j] - iou;
            local += dc * dc * (5.0f / 8.0f);                       // OBJ_SCALE/B

            float ddx = p.x - l.x, ddy = p.y - l.y;
            local += (ddx * ddx + ddy * ddy) * (3.0f / 8.0f);       // L_COORD/B
            local += (huber(p.z - l.z) + huber(p.w - l.w)) * (3.0f / 8.0f);

            const float* lcr = label_cls + 20 * j;
            const float* pcr = pred_cls  + 20 * j;
            int lbl = 0;
            float bm = lcr[0];
            float mx = pcr[0];
            #pragma unroll
            for (int c = 1; c < 20; c++) {
                float lv = lcr[c];
                if (lv > bm) { bm = lv; lbl = c; }
                mx = fmaxf(mx, pcr[c]);
            }
            float ssum = 0.f;
            #pragma unroll
            for (int c = 0; c < 20; c++) ssum += __expf(pcr[c] - mx);
            local += -(pcr[lbl] - mx - __logf(ssum)) * (1.0f / 8.0f);
        } else if (bestm < cp) {
            float d = pred_conf[j] - lconf;
            local += d * d * (1.0f / 8.0f);                          // NOOBJ_SCALE/B
        }
    }

    // ---------- block reduction ----------
    int lane = tid & 31;
    int wid  = tid >> 5;
    #pragma unroll
    for (int off = 16; off > 0; off >>= 1)
        local += __shfl_down_sync(0xffffffffu, local, off);
    if (lane == 0) s_red[wid] = local;
    __syncthreads();

    if (wid == 0) {
        float v = (lane < 16) ? s_red[lane] : 0.f;
        #pragma unroll
        for (int off = 8; off > 0; off >>= 1)
            v += __shfl_down_sync(0xffffffffu, v, off);
        if (lane == 0) {
            atomicAdd(&g_sum, v);
            __threadfence();
            unsigned t = atomicAdd(&g_tickets, 1u);
            if (t == (unsigned)(gridDim.x - 1)) {
                float total = atomicExch(&g_sum, 0.f);
                atomicExch(&g_tickets, 0u);
                *out = total;
            }
        }
    }
}

extern "C" void kernel_launch(void* const* d_in, const int* in_sizes, int n_in,
                              void* d_out, int out_size)
{
    const float* pred_cls   = (const float*)d_in[0];
    const float* pred_conf  = (const float*)d_in[1];
    const float* pred_bb    = (const float*)d_in[2];
    const float* label_cls  = (const float*)d_in[3];
    const float* label_conf = (const float*)d_in[4];
    const float* label_bb   = (const float*)d_in[5];
    float* out = (float*)d_out;

    yolo_one<<<NBLK, NT>>>(pred_cls, pred_conf, pred_bb,
                           label_cls, label_conf, label_bb, out);
}

// round 11
// speedup vs baseline: 3.4704x; 1.1268x over previous
#include <cuda_runtime.h>
#include <cuda_bf16.h>
#include <math.h>

// Fixed problem shape: B=8, H=W=13, A=5, C=20
#define NN     6760        // B*H*W*A
#define MAXPOS 512         // ~135 expected positives (2%)

// k1 grid
#define NT1    256
#define NBLK1  27          // 27*256 = 6912 >= 6760
// k2 grid
#define NT2    512
#define PPB    32          // preds per block
#define LPG    16          // lanes per pred group (32*16 = 512)
#define NBLK2  212         // ceil(6760/32)

static __constant__ float c_anchors[10] = {
    1.3221f, 1.73145f,
    3.19275f, 4.00944f,
    5.05587f, 8.09892f,
    9.47112f, 4.84053f,
    11.2364f, 10.0071f
};

// Device scratch (zero-init at load; k2's last block resets -> replay-safe)
__device__ float4   g_posbox[MAXPOS];  // (gx, gy, gx2, gy2)
__device__ float    g_posc[MAXPOS];    // 0.6 * a1
__device__ int      g_pcnt    = 0;
__device__ float    g_sum     = 0.f;
__device__ unsigned g_tickets = 0u;

__device__ __forceinline__ float huber(float d) {
    float ad = fabsf(d);
    return (ad < 1.0f) ? 0.5f * d * d : ad - 0.5f;
}

// ---------------- k1: scan + compact + decode positives (once, chip-wide) ----
__global__ void __launch_bounds__(NT1)
k_scan(const float* __restrict__ label_conf,
       const float* __restrict__ label_bb)
{
    int idx = blockIdx.x * NT1 + threadIdx.x;
    if (idx >= NN) return;
    float c = label_conf[idx];
    if (c > 0.f) {
        const float inv = 1.0f / 13.0f;
        float4 l = ((const float4*)label_bb)[idx];
        int a = idx % 5;
        int w = (idx / 5)  % 13;
        int h = (idx / 65) % 13;
        float gw = __expf(l.z) * c_anchors[2*a]     * inv;
        float gh = __expf(l.w) * c_anchors[2*a + 1] * inv;
        float gx = (l.x + (float)w) * inv - 0.5f * gw;
        float gy = (l.y + (float)h) * inv - 0.5f * gh;
        float gx2 = gx + gw, gy2 = gy + gh;
        int slot = atomicAdd(&g_pcnt, 1);
        if (slot < MAXPOS) {
            g_posbox[slot] = make_float4(gx, gy, gx2, gy2);
            g_posc[slot]   = 0.6f * ((gx2 - gx) * (gy2 - gy));
        }
    }
}

// ---------------- k2: all losses, wide ---------------------------------------
__global__ void __launch_bounds__(NT2)
k_loss(const float* __restrict__ pred_cls,
       const float* __restrict__ pred_conf,
       const float* __restrict__ pred_bb,
       const float* __restrict__ label_cls,
       const float* __restrict__ label_conf,
       const float* __restrict__ label_bb,
       float* __restrict__ out)
{
    __shared__ float4 s_pos[MAXPOS];
    __shared__ float  s_c[MAXPOS];
    __shared__ float  s_red[16];

    const float inv = 1.0f / 13.0f;
    const float4* pbb4 = (const float4*)pred_bb;
    const float4* lbb4 = (const float4*)label_bb;

    int tid = threadIdx.x;
    int g   = tid & (LPG - 1);
    int pr  = tid >> 4;                 // 0..31
    int j   = blockIdx.x * PPB + pr;
    bool valid = j < NN;

    // prefetch pred box + conf immediately (in flight during staging)
    float4 p = make_float4(0.f, 0.f, 0.f, 0.f);
    float lconf = 0.f;
    if (valid) { p = pbb4[j]; lconf = label_conf[j]; }

    // stage positive list (L2-broadcast, one latency round)
    int npos = min(g_pcnt, MAXPOS);
    if (tid < npos) { s_pos[tid] = g_posbox[tid]; s_c[tid] = g_posc[tid]; }
    __syncthreads();

    float local = 0.f;
    float bestm = -1e30f;
    float px = 0.f, py = 0.f, px2 = 0.f, py2 = 0.f, cp = 0.f;
    float anc_w = 0.f, anc_h = 0.f;
    int w = 0, h = 0;

    if (valid) {
        int a = j % 5;
        w = (j / 5)  % 13;
        h = (j / 65) % 13;
        anc_w = c_anchors[2*a]; anc_h = c_anchors[2*a + 1];
        float pw = __expf(p.z) * anc_w * inv;
        float ph = __expf(p.w) * anc_h * inv;
        px = (p.x + (float)w) * inv - 0.5f * pw;
        py = (p.y + (float)h) * inv - 0.5f * ph;
        px2 = px + pw; py2 = py + ph;
        cp = 0.6f * ((px2 - px) * (py2 - py));   // 0.6 * a2 (pairwise convention)

        // division-free: best iou < 0.6  <=>  max(1.6*inter - 0.6*a1) < 0.6*a2
        for (int k = g; k < npos; k += LPG) {
            float4 gb = s_pos[k];
            float dx = fmaxf(fminf(gb.z, px2) - fmaxf(gb.x, px), 0.f);
            float dy = fmaxf(fminf(gb.w, py2) - fmaxf(gb.y, py), 0.f);
            bestm = fmaxf(bestm, fmaf(1.6f, dx * dy, -s_c[k]));
        }
    }
    bestm = fmaxf(bestm, __shfl_xor_sync(0xffffffffu, bestm, 1, LPG));
    bestm = fmaxf(bestm, __shfl_xor_sync(0xffffffffu, bestm, 2, LPG));
    bestm = fmaxf(bestm, __shfl_xor_sync(0xffffffffu, bestm, 4, LPG));
    bestm = fmaxf(bestm, __shfl_xor_sync(0xffffffffu, bestm, 8, LPG));

    if (g == 0 && valid) {
        if (lconf > 0.f) {
            // ---- positive-anchor losses (~2% of preds) ----
            float4 l = lbb4[j];
            float gw = __expf(l.z) * anc_w * inv;
            float gh = __expf(l.w) * anc_h * inv;
            float gx = (l.x + (float)w) * inv - 0.5f * gw;
            float gy = (l.y + (float)h) * inv - 0.5f * gh;

            float gx2 = gx + gw, gy2 = gy + gh;
            float pw = px2 - px, ph = py2 - py;
            float dx = fmaxf(fminf(gx2, px2) - fmaxf(gx, px), 0.f);
            float dy = fmaxf(fminf(gy2, py2) - fmaxf(gy, py), 0.f);
            float inter = dx * dy;
            float iou = inter / (gw * gh + pw * ph - inter);

            float dc = pred_conf[j] - iou;
            local += dc * dc * (5.0f / 8.0f);                       // OBJ_SCALE/B

            float ddx = p.x - l.x, ddy = p.y - l.y;
            local += (ddx * ddx + ddy * ddy) * (3.0f / 8.0f);       // L_COORD/B
            local += (huber(p.z - l.z) + huber(p.w - l.w)) * (3.0f / 8.0f);

            // class NLL: first-max argmax(label_cls), -log_softmax(pred_cls)[lbl]
            const float* lcr = label_cls + 20 * j;
            const float* pcr = pred_cls  + 20 * j;
            int lbl = 0;
            float bm = lcr[0];
            float mx = pcr[0];
            #pragma unroll
            for (int c = 1; c < 20; c++) {
                float lv = lcr[c];
                if (lv > bm) { bm = lv; lbl = c; }
                mx = fmaxf(mx, pcr[c]);
            }
            float ssum = 0.f;
            #pragma unroll
            for (int c = 0; c < 20; c++) ssum += __expf(pcr[c] - mx);
            local += -(pcr[lbl] - mx - __logf(ssum)) * (1.0f / 8.0f);
        } else if (bestm < cp) {
            // ---- negative-conf loss ----
            float d = pred_conf[j] - lconf;
            local += d * d * (1.0f / 8.0f);                          // NOOBJ_SCALE/B
        }
    }

    // ---------- block reduction ----------
    int lane = tid & 31;
    int wid  = tid >> 5;
    #pragma unroll
    for (int off = 16; off > 0; off >>= 1)
        local += __shfl_down_sync(0xffffffffu, local, off);
    if (lane == 0) s_red[wid] = local;
    __syncthreads();

    if (wid == 0) {
        float v = (lane < 16) ? s_red[lane] : 0.f;
        #pragma unroll
        for (int off = 8; off > 0; off >>= 1)
            v += __shfl_down_sync(0xffffffffu, v, off);
        if (lane == 0) {
            atomicAdd(&g_sum, v);
            __threadfence();
            unsigned t = atomicAdd(&g_tickets, 1u);
            if (t == (unsigned)(gridDim.x - 1)) {
                // last block: publish result, reset ALL scratch for next replay
                float total = atomicExch(&g_sum, 0.f);
                atomicExch(&g_tickets, 0u);
                atomicExch(&g_pcnt, 0);
                *out = total;
            }
        }
    }
}

extern "C" void kernel_launch(void* const* d_in, const int* in_sizes, int n_in,
                              void* d_out, int out_size)
{
    const float* pred_cls   = (const float*)d_in[0];
    const float* pred_conf  = (const float*)d_in[1];
    const float* pred_bb    = (const float*)d_in[2];
    const float* label_cls  = (const float*)d_in[3];
    const float* label_conf = (const float*)d_in[4];
    const float* label_bb   = (const float*)d_in[5];
    float* out = (float*)d_out;

    k_scan<<<NBLK1, NT1>>>(label_conf, label_bb);
    k_loss<<<NBLK2, NT2>>>(pred_cls, pred_conf, pred_bb,
                           label_cls, label_conf, label_bb, out);
}